// round 14
// baseline (speedup 1.0000x reference)
#include <cuda_runtime.h>
#include <cuda_bf16.h>
#include <math.h>
#include <stdint.h>

#define BN_ 4096
#define KN_ 32
#define DN_ 256
#define DH_ 128
#define NREL_ 9
#define INV_T 14.285714285714286f
#define TSK 136  // sim smem stride (128 + 8 pad)
#define TSF 264  // fused-proj smem stride (256 + 8 pad)
#define SIM_TILE_B (128 * TSK * 2)   // 34816 bytes per 128x128 tile

typedef __nv_bfloat16 bf16;

// ---------------- scratch ----------------
__device__ __align__(16) bf16 g_v1[BN_ * DN_];
__device__ __align__(16) bf16 g_v2[BN_ * DN_];
__device__ __align__(16) bf16 g_z1[BN_ * DH_];
__device__ __align__(16) bf16 g_z2[BN_ * DH_];
__device__ __align__(16) bf16 g_w1at[DN_ * DN_];
__device__ __align__(16) bf16 g_w1bt[DH_ * DN_];
__device__ __align__(16) bf16 g_w2at[DN_ * DN_];
__device__ __align__(16) bf16 g_w2bt[DH_ * DN_];
__device__ float g_rowsum[BN_];
__device__ float g_colsum[BN_];
__device__ float g_diag[BN_];
__device__ int   g_mask_u8;

// ---------------- async-copy / ldmatrix / mma primitives ----------------
__device__ __forceinline__ void cp16(uint32_t s, const void* g) {
    asm volatile("cp.async.cg.shared.global [%0], [%1], 16;\n" :: "r"(s), "l"(g));
}
__device__ __forceinline__ void cpcommit() {
    asm volatile("cp.async.commit_group;\n" ::: "memory");
}
template <int N>
__device__ __forceinline__ void cpwait() {
    asm volatile("cp.async.wait_group %0;\n" :: "n"(N) : "memory");
}
__device__ __forceinline__ void ldsm4(unsigned r[4], uint32_t a) {
    asm volatile("ldmatrix.sync.aligned.m8n8.x4.shared.b16 {%0,%1,%2,%3}, [%4];\n"
                 : "=r"(r[0]), "=r"(r[1]), "=r"(r[2]), "=r"(r[3]) : "r"(a));
}
__device__ __forceinline__ void mma16816(float c[4], unsigned a0, unsigned a1, unsigned a2, unsigned a3,
                                         unsigned b0, unsigned b1) {
    asm volatile("mma.sync.aligned.m16n8k16.row.col.f32.bf16.bf16.f32 "
                 "{%0,%1,%2,%3}, {%4,%5,%6,%7}, {%8,%9}, {%0,%1,%2,%3};\n"
                 : "+f"(c[0]), "+f"(c[1]), "+f"(c[2]), "+f"(c[3])
                 : "r"(a0), "r"(a1), "r"(a2), "r"(a3), "r"(b0), "r"(b1));
}

// ---------------- prep: mask detect + zero + tiled weight transpose (bf16) ----------------
__global__ void prep_kernel(const float* __restrict__ W1a, const float* __restrict__ W1b,
                            const float* __restrict__ W2a, const float* __restrict__ W2b,
                            const unsigned int* __restrict__ m1) {
    int blk = blockIdx.x;
    int t = threadIdx.x;

    int zi = blk * 256 + t;
    if (zi < BN_) { g_rowsum[zi] = 0.f; g_colsum[zi] = 0.f; }

    __shared__ int sf;
    if (t == 0) sf = 0;
    __syncthreads();
    if (blk == 0) {
        int f = 0;
        for (int i = t; i < 4096; i += 256)
            if (m1[i] > 1u) f = 1;
        if (f) sf = 1;
    }
    __syncthreads();
    if (blk == 0 && t == 0) g_mask_u8 = sf;

    const float* W; bf16* Th; int N, tile;
    const int K = DN_;
    if (blk < 16)      { W = W1a; Th = g_w1at; N = 256; tile = blk; }
    else if (blk < 24) { W = W1b; Th = g_w1bt; N = 128; tile = blk - 16; }
    else if (blk < 40) { W = W2a; Th = g_w2at; N = 256; tile = blk - 24; }
    else               { W = W2b; Th = g_w2bt; N = 128; tile = blk - 40; }
    int tn = N / 64;
    int k0 = (tile / tn) * 64, n0 = (tile % tn) * 64;

    __shared__ float s[64][65];
#pragma unroll
    for (int i = 0; i < 16; i++) {
        int idx = t + i * 256;
        int r = idx >> 6, c = idx & 63;
        s[r][c] = W[(size_t)(k0 + r) * N + n0 + c];
    }
    __syncthreads();
#pragma unroll
    for (int i = 0; i < 16; i++) {
        int idx = t + i * 256;
        int n = idx >> 6, k = idx & 63;
        Th[(size_t)(n0 + n) * K + k0 + k] = __float2bfloat16(s[k][n]);
    }
}

// ---------------- aggregation: cp.async-staged compacted gather ----------------
__global__ void aggregate_kernel(const float* __restrict__ nf,
                                 const float* __restrict__ rel,
                                 const int* __restrict__ nb1, const int* __restrict__ rl1, const void* __restrict__ m1,
                                 const int* __restrict__ nb2, const int* __restrict__ rl2, const void* __restrict__ m2,
                                 const int* __restrict__ selfids) {
    int b = blockIdx.x;
    const int* nb; const int* rl; const void* m; bf16* oh;
    if (b < BN_) { nb = nb1; rl = rl1; m = m1; oh = g_v1; }
    else         { b -= BN_; nb = nb2; rl = rl2; m = m2; oh = g_v2; }

    __shared__ int s_nb[KN_];
    __shared__ float s_rcnt[16];
    __shared__ int s_cnt;
    __shared__ __align__(16) float s_stage[KN_ * DN_];   // 32 KB
    int t = threadIdx.x;
    if (t < 16) s_rcnt[t] = 0.f;
    __syncthreads();
    if (t < KN_) {   // warp 0: mask decode + compaction + relation counts
        int mk;
        if (g_mask_u8) mk = ((const unsigned char*)m)[b * KN_ + t];
        else           mk = ((const int*)m)[b * KN_ + t];
        mk = (mk != 0);
        int nbv = nb[b * KN_ + t];
        int rlv = rl[b * KN_ + t];
        unsigned bal = __ballot_sync(0xFFFFFFFFu, mk);
        if (mk) {
            int pos = __popc(bal & ((1u << t) - 1u));
            s_nb[pos] = nbv;
            atomicAdd(&s_rcnt[rlv], 1.f);
        }
        if (t == 0) s_cnt = __popc(bal);
    }
    __syncthreads();
    int cnt = s_cnt;

    // stage all masked neighbor rows into smem via cp.async (no LDG scoreboard serialization)
    uint32_t sst = (uint32_t)__cvta_generic_to_shared(s_stage);
    for (int idx = t; idx < cnt * 64; idx += 256) {
        int row = idx >> 6, seg = idx & 63;
        cp16(sst + (uint32_t)(row * DN_ + seg * 4) * 4,
             nf + (size_t)s_nb[row] * DN_ + seg * 4);
    }
    cpcommit();
    cpwait<0>();
    __syncthreads();

    int d = t;
    float a0 = 0.f, a1 = 0.f, a2 = 0.f, a3 = 0.f;
    int k = 0;
    for (; k + 3 < cnt; k += 4) {
        a0 += s_stage[(k + 0) * DN_ + d];
        a1 += s_stage[(k + 1) * DN_ + d];
        a2 += s_stage[(k + 2) * DN_ + d];
        a3 += s_stage[(k + 3) * DN_ + d];
    }
    for (; k < cnt; k++) a0 += s_stage[k * DN_ + d];
    float acc = (a0 + a1) + (a2 + a3);
#pragma unroll
    for (int r = 0; r < NREL_; r++)
        acc = fmaf(s_rcnt[r], rel[r * DN_ + d], acc);
    float res;
    if (cnt > 0) res = acc / (float)cnt;
    else         res = nf[(size_t)selfids[b] * DN_ + d];
    oh[(size_t)b * DN_ + d] = __float2bfloat16(res);
}

// ---------------- fused proj: h = relu(v@Wa^T+ba); z = normalize(h@Wb^T+bb) ----------------
#define SV_OFF 0
#define SH_OFF 33792
#define SW0_OFF 67584
#define SW1_OFF 101376
#define FPROJ_SMEM 135168

__device__ __forceinline__ void load_rows64(uint32_t sdst, const bf16* gsrc, int tid) {
#pragma unroll
    for (int i = 0; i < 8; i++) {
        int e = tid + i * 256;
        int row = e >> 5, seg = e & 31;
        cp16(sdst + (uint32_t)(row * TSF + seg * 8) * 2, gsrc + (size_t)row * DN_ + seg * 8);
    }
}

__global__ void __launch_bounds__(256, 1) fused_proj_kernel(
        const float* __restrict__ b1a, const float* __restrict__ b2a,
        const float* __restrict__ b1b, const float* __restrict__ b2b) {
    extern __shared__ char smem_dyn[];
    __shared__ float s_ss[64];
    uint32_t sb = (uint32_t)__cvta_generic_to_shared(smem_dyn);
    uint32_t sV = sb + SV_OFF, sH = sb + SH_OFF;
    uint32_t sW[2] = { sb + SW0_OFF, sb + SW1_OFF };

    int tid = threadIdx.x;
    int lane = tid & 31, w = tid >> 5;
    int wr = w >> 1, wc = w & 1;
    int grp = lane >> 2, qp = (lane & 3) * 2;
    int bm = blockIdx.x * 64;
    int view = blockIdx.z;
    const bf16* V  = view ? g_v2 : g_v1;
    const bf16* Wa = view ? g_w2at : g_w1at;
    const bf16* Wb = view ? g_w2bt : g_w1bt;
    const float* ba = view ? b2a : b1a;
    const float* bb = view ? b2b : b1b;
    bf16* Z = view ? g_z2 : g_z1;

    if (tid < 64) s_ss[tid] = 0.f;

    int rowA = (lane & 7) + ((lane >> 3) & 1) * 8;
    int kA   = (lane >> 4) * 8;
    int rowB = (lane & 7) + (lane >> 4) * 8;
    int kB   = ((lane >> 3) & 1) * 8;

    load_rows64(sV, V + (size_t)bm * DN_, tid);
    load_rows64(sW[0], Wa, tid);
    cpcommit();

    float c2[2][4][4] = {};

    // -------- phase 1: h = relu(v @ Wa^T + ba) --------
#pragma unroll 1
    for (int c = 0; c < 4; c++) {
        cpwait<0>();
        __syncthreads();
        if (c < 3)      load_rows64(sW[(c + 1) & 1], Wa + (size_t)(c + 1) * 64 * DN_, tid);
        else            load_rows64(sW[(c + 1) & 1], Wb, tid);
        cpcommit();

        uint32_t sWc = sW[c & 1];
        float c1[4][4] = {};
#pragma unroll
        for (int kk = 0; kk < 256; kk += 16) {
            unsigned a[4];
            ldsm4(a, sV + (uint32_t)((wr * 16 + rowA) * TSF + kk + kA) * 2);
            unsigned bfrag[4][2];
#pragma unroll
            for (int np = 0; np < 2; np++) {
                unsigned r[4];
                ldsm4(r, sWc + (uint32_t)((wc * 32 + np * 16 + rowB) * TSF + kk + kB) * 2);
                bfrag[2 * np][0] = r[0]; bfrag[2 * np][1] = r[1];
                bfrag[2 * np + 1][0] = r[2]; bfrag[2 * np + 1][1] = r[3];
            }
#pragma unroll
            for (int ns = 0; ns < 4; ns++)
                mma16816(c1[ns], a[0], a[1], a[2], a[3], bfrag[ns][0], bfrag[ns][1]);
        }
#pragma unroll
        for (int ns = 0; ns < 4; ns++) {
            int col = c * 64 + wc * 32 + ns * 8 + qp;
            float bias0 = ba[col], bias1 = ba[col + 1];
#pragma unroll
            for (int h = 0; h < 2; h++) {
                int row = wr * 16 + grp + 8 * h;
                float v0 = fmaxf(c1[ns][2 * h + 0] + bias0, 0.f);
                float v1 = fmaxf(c1[ns][2 * h + 1] + bias1, 0.f);
                __nv_bfloat162 hp;
                hp.x = __float2bfloat16(v0); hp.y = __float2bfloat16(v1);
                *(__nv_bfloat162*)(smem_dyn + SH_OFF + (size_t)(row * TSF + col) * 2) = hp;
            }
        }
    }

    // -------- phase 2: z = h @ Wb^T + bb --------
#pragma unroll 1
    for (int c = 0; c < 2; c++) {
        cpwait<0>();
        __syncthreads();
        if (c < 1) { load_rows64(sW[(4 + c + 1) & 1], Wb + (size_t)64 * DN_, tid); cpcommit(); }

        uint32_t sWc = sW[(4 + c) & 1];
#pragma unroll
        for (int kk = 0; kk < 256; kk += 16) {
            unsigned a[4];
            ldsm4(a, sH + (uint32_t)((wr * 16 + rowA) * TSF + kk + kA) * 2);
            unsigned bfrag[4][2];
#pragma unroll
            for (int np = 0; np < 2; np++) {
                unsigned r[4];
                ldsm4(r, sWc + (uint32_t)((wc * 32 + np * 16 + rowB) * TSF + kk + kB) * 2);
                bfrag[2 * np][0] = r[0]; bfrag[2 * np][1] = r[1];
                bfrag[2 * np + 1][0] = r[2]; bfrag[2 * np + 1][1] = r[3];
            }
#pragma unroll
            for (int ns = 0; ns < 4; ns++)
                mma16816(c2[c][ns], a[0], a[1], a[2], a[3], bfrag[ns][0], bfrag[ns][1]);
        }
    }

    float vv[2][4][4];
#pragma unroll
    for (int c = 0; c < 2; c++)
#pragma unroll
        for (int ns = 0; ns < 4; ns++) {
            int col = c * 64 + wc * 32 + ns * 8 + qp;
            float bias0 = bb[col], bias1 = bb[col + 1];
#pragma unroll
            for (int h = 0; h < 2; h++) {
                vv[c][ns][2 * h + 0] = c2[c][ns][2 * h + 0] + bias0;
                vv[c][ns][2 * h + 1] = c2[c][ns][2 * h + 1] + bias1;
            }
        }
#pragma unroll
    for (int h = 0; h < 2; h++) {
        float ss = 0.f;
#pragma unroll
        for (int c = 0; c < 2; c++)
#pragma unroll
            for (int ns = 0; ns < 4; ns++) {
                float a = vv[c][ns][2 * h + 0], b = vv[c][ns][2 * h + 1];
                ss = fmaf(a, a, ss); ss = fmaf(b, b, ss);
            }
        ss += __shfl_xor_sync(0xFFFFFFFFu, ss, 1);
        ss += __shfl_xor_sync(0xFFFFFFFFu, ss, 2);
        if ((lane & 3) == 0)
            atomicAdd(&s_ss[wr * 16 + grp + 8 * h], ss);
    }
    __syncthreads();

#pragma unroll
    for (int h = 0; h < 2; h++) {
        int rloc = wr * 16 + grp + 8 * h;
        float rinv = rsqrtf(s_ss[rloc]);
        int row = bm + rloc;
#pragma unroll
        for (int c = 0; c < 2; c++)
#pragma unroll
            for (int ns = 0; ns < 4; ns++) {
                int col = c * 64 + wc * 32 + ns * 8 + qp;
                float v0 = vv[c][ns][2 * h + 0] * rinv;
                float v1 = vv[c][ns][2 * h + 1] * rinv;
                __nv_bfloat162 hp;
                hp.x = __float2bfloat16(v0); hp.y = __float2bfloat16(v1);
                *(__nv_bfloat162*)(Z + (size_t)row * DH_ + col) = hp;
            }
    }
}

// ---------------- sim: 2 bn-tiles per CTA, A reused, loads fully prefetched ----------------
// grid (32, 16): bm = bx*128; bn tiles at by*256 and by*256+128.
__global__ void __launch_bounds__(256, 2) sim_lse_kernel() {
    extern __shared__ char smem_dyn[];
    __shared__ float s_rs[128], s_cs[2][128];
    int tid = threadIdx.x;
    int lane = tid & 31, w = tid >> 5;
    int wr = w >> 2, wc = w & 3;
    int grp = lane >> 2, qp = (lane & 3) * 2;
    int bm = blockIdx.x * 128, bn0 = blockIdx.y * 256;
    if (tid < 128) { s_rs[tid] = 0.f; s_cs[0][tid] = 0.f; s_cs[1][tid] = 0.f; }

    uint32_t sA = (uint32_t)__cvta_generic_to_shared(smem_dyn);
    uint32_t sB[2] = { sA + SIM_TILE_B, sA + 2 * SIM_TILE_B };

    // issue ALL loads up front: A + B0 (group 0), B1 (group 1)
#pragma unroll
    for (int i = 0; i < 8; i++) {
        int idx = tid + i * 256;
        int row = idx >> 4, seg = idx & 15;
        uint32_t so = (uint32_t)(row * TSK + seg * 8) * 2;
        cp16(sA + so,    g_z1 + (size_t)(bm + row) * DH_ + seg * 8);
        cp16(sB[0] + so, g_z2 + (size_t)(bn0 + row) * DH_ + seg * 8);
    }
    cpcommit();
#pragma unroll
    for (int i = 0; i < 8; i++) {
        int idx = tid + i * 256;
        int row = idx >> 4, seg = idx & 15;
        cp16(sB[1] + (uint32_t)(row * TSK + seg * 8) * 2,
             g_z2 + (size_t)(bn0 + 128 + row) * DH_ + seg * 8);
    }
    cpcommit();

    int rowA = (lane & 7) + ((lane >> 3) & 1) * 8;
    int kA   = (lane >> 4) * 8;
    int rowB = (lane & 7) + (lane >> 4) * 8;
    int kB   = ((lane >> 3) & 1) * 8;

    float rs[4][2] = {};   // row sums persist across both tiles

#pragma unroll 1
    for (int j = 0; j < 2; j++) {
        if (j == 0) { cpwait<1>(); } else { cpwait<0>(); }
        __syncthreads();
        int bn = bn0 + j * 128;
        uint32_t sBj = sB[j];

        float c[4][4][4] = {};
#pragma unroll
        for (int kk = 0; kk < 128; kk += 16) {
            unsigned a[4][4];
#pragma unroll
            for (int ms = 0; ms < 4; ms++)
                ldsm4(a[ms], sA + (uint32_t)(((wr * 4 + ms) * 16 + rowA) * TSK + kk + kA) * 2);
            unsigned bfr[4][2];
#pragma unroll
            for (int np = 0; np < 2; np++) {
                unsigned r[4];
                ldsm4(r, sBj + (uint32_t)((wc * 32 + np * 16 + rowB) * TSK + kk + kB) * 2);
                bfr[2 * np][0] = r[0]; bfr[2 * np][1] = r[1];
                bfr[2 * np + 1][0] = r[2]; bfr[2 * np + 1][1] = r[3];
            }
#pragma unroll
            for (int ms = 0; ms < 4; ms++)
#pragma unroll
                for (int ns = 0; ns < 4; ns++)
                    mma16816(c[ms][ns], a[ms][0], a[ms][1], a[ms][2], a[ms][3], bfr[ns][0], bfr[ns][1]);
        }

        float cs[4][2] = {};
#pragma unroll
        for (int ms = 0; ms < 4; ms++) {
#pragma unroll
            for (int ns = 0; ns < 4; ns++) {
#pragma unroll
                for (int r = 0; r < 4; r++) {
                    int h = r >> 1, p = r & 1;
                    int row = bm + (wr * 4 + ms) * 16 + grp + 8 * h;
                    int col = bn + wc * 32 + ns * 8 + qp + p;
                    float s = c[ms][ns][r] * INV_T;
                    if (row == col) g_diag[row] = s;
                    float ev = __expf(s - INV_T);
                    rs[ms][h] += ev;
                    cs[ns][p] += ev;
                }
            }
        }
        // col sums for this tile
#pragma unroll
        for (int ns = 0; ns < 4; ns++)
#pragma unroll
            for (int p = 0; p < 2; p++) {
                float v = cs[ns][p];
                v += __shfl_xor_sync(0xFFFFFFFFu, v, 4);
                v += __shfl_xor_sync(0xFFFFFFFFu, v, 8);
                v += __shfl_xor_sync(0xFFFFFFFFu, v, 16);
                if (grp == 0)
                    atomicAdd(&s_cs[j][wc * 32 + ns * 8 + qp + p], v);
            }
    }

    // row sums (both tiles accumulated)
#pragma unroll
    for (int ms = 0; ms < 4; ms++)
#pragma unroll
        for (int h = 0; h < 2; h++) {
            float v = rs[ms][h];
            v += __shfl_xor_sync(0xFFFFFFFFu, v, 1);
            v += __shfl_xor_sync(0xFFFFFFFFu, v, 2);
            if ((lane & 3) == 0)
                atomicAdd(&s_rs[(wr * 4 + ms) * 16 + grp + 8 * h], v);
        }
    __syncthreads();
    if (tid < 128) {
        atomicAdd(&g_rowsum[bm + tid], s_rs[tid]);
        atomicAdd(&g_colsum[bn0 + tid], s_cs[0][tid]);
        atomicAdd(&g_colsum[bn0 + 128 + tid], s_cs[1][tid]);
    }
}

// ---------------- final loss reduce ----------------
__global__ void loss_kernel(float* __restrict__ out) {
    float acc = 0.f;
    for (int i = threadIdx.x; i < BN_; i += 256) {
        acc += 0.5f * (logf(g_rowsum[i]) + logf(g_colsum[i])) + INV_T - g_diag[i];
    }
#pragma unroll
    for (int off = 16; off; off >>= 1) acc += __shfl_xor_sync(0xFFFFFFFFu, acc, off);
    __shared__ float wsum[8];
    if ((threadIdx.x & 31) == 0) wsum[threadIdx.x >> 5] = acc;
    __syncthreads();
    if (threadIdx.x == 0) {
        float tot = 0.f;
        for (int k = 0; k < 8; k++) tot += wsum[k];
        out[0] = tot / (float)BN_;
    }
}

// ---------------- launch ----------------
extern "C" void kernel_launch(void* const* d_in, const int* in_sizes, int n_in,
                              void* d_out, int out_size) {
    const float* nf   = (const float*)d_in[0];
    const float* rel  = (const float*)d_in[1];
    const int*   nb1  = (const int*)d_in[2];
    const int*   rl1  = (const int*)d_in[3];
    const void*  m1   = d_in[4];
    const int*   nb2  = (const int*)d_in[5];
    const int*   rl2  = (const int*)d_in[6];
    const void*  m2   = d_in[7];
    const int*   self_ = (const int*)d_in[8];
    const float* W1a  = (const float*)d_in[9];
    const float* b1a  = (const float*)d_in[10];
    const float* W1b  = (const float*)d_in[11];
    const float* b1b  = (const float*)d_in[12];
    const float* W2a  = (const float*)d_in[13];
    const float* b2a  = (const float*)d_in[14];
    const float* W2b  = (const float*)d_in[15];
    const float* b2b  = (const float*)d_in[16];

    const int smemS = 3 * SIM_TILE_B;   // 104448
    cudaFuncSetAttribute(fused_proj_kernel, cudaFuncAttributeMaxDynamicSharedMemorySize, FPROJ_SMEM);
    cudaFuncSetAttribute(sim_lse_kernel,    cudaFuncAttributeMaxDynamicSharedMemorySize, smemS);

    prep_kernel<<<48, 256>>>(W1a, W1b, W2a, W2b, (const unsigned int*)m1);
    aggregate_kernel<<<2 * BN_, 256>>>(nf, rel, nb1, rl1, m1, nb2, rl2, m2, self_);
    fused_proj_kernel<<<dim3(64, 1, 2), 256, FPROJ_SMEM>>>(b1a, b2a, b1b, b2b);
    sim_lse_kernel<<<dim3(32, 16), 256, smemS>>>();
    loss_kernel<<<1, 256>>>((float*)d_out);
}

// round 15
// speedup vs baseline: 1.1340x; 1.1340x over previous
#include <cuda_runtime.h>
#include <cuda_bf16.h>
#include <math.h>
#include <stdint.h>

#define BN_ 4096
#define KN_ 32
#define DN_ 256
#define DH_ 128
#define NREL_ 9
#define INV_T 14.285714285714286f
#define TSK 136  // sim smem stride (128 + 8 pad)
#define TSF 264  // fused-proj smem stride (256 + 8 pad)
#define SIM_TILE_B (128 * TSK * 2)   // 34816 bytes per 128x128 tile

typedef __nv_bfloat16 bf16;

// ---------------- scratch ----------------
__device__ __align__(16) bf16 g_v1[BN_ * DN_];
__device__ __align__(16) bf16 g_v2[BN_ * DN_];
__device__ __align__(16) bf16 g_z1[BN_ * DH_];
__device__ __align__(16) bf16 g_z2[BN_ * DH_];
__device__ __align__(16) bf16 g_w1at[DN_ * DN_];
__device__ __align__(16) bf16 g_w1bt[DH_ * DN_];
__device__ __align__(16) bf16 g_w2at[DN_ * DN_];
__device__ __align__(16) bf16 g_w2bt[DH_ * DN_];
__device__ float g_rowsum[BN_];
__device__ float g_colsum[BN_];
__device__ float g_diag[BN_];
__device__ int   g_mask_u8;

// ---------------- async-copy / ldmatrix / mma primitives ----------------
__device__ __forceinline__ void cp16(uint32_t s, const void* g) {
    asm volatile("cp.async.cg.shared.global [%0], [%1], 16;\n" :: "r"(s), "l"(g));
}
__device__ __forceinline__ void cpcommit() {
    asm volatile("cp.async.commit_group;\n" ::: "memory");
}
template <int N>
__device__ __forceinline__ void cpwait() {
    asm volatile("cp.async.wait_group %0;\n" :: "n"(N) : "memory");
}
__device__ __forceinline__ void ldsm4(unsigned r[4], uint32_t a) {
    asm volatile("ldmatrix.sync.aligned.m8n8.x4.shared.b16 {%0,%1,%2,%3}, [%4];\n"
                 : "=r"(r[0]), "=r"(r[1]), "=r"(r[2]), "=r"(r[3]) : "r"(a));
}
__device__ __forceinline__ void mma16816(float c[4], unsigned a0, unsigned a1, unsigned a2, unsigned a3,
                                         unsigned b0, unsigned b1) {
    asm volatile("mma.sync.aligned.m16n8k16.row.col.f32.bf16.bf16.f32 "
                 "{%0,%1,%2,%3}, {%4,%5,%6,%7}, {%8,%9}, {%0,%1,%2,%3};\n"
                 : "+f"(c[0]), "+f"(c[1]), "+f"(c[2]), "+f"(c[3])
                 : "r"(a0), "r"(a1), "r"(a2), "r"(a3), "r"(b0), "r"(b1));
}

// ---------------- prep: mask detect + zero + tiled weight transpose (bf16) ----------------
__global__ void prep_kernel(const float* __restrict__ W1a, const float* __restrict__ W1b,
                            const float* __restrict__ W2a, const float* __restrict__ W2b,
                            const unsigned int* __restrict__ m1) {
    int blk = blockIdx.x;
    int t = threadIdx.x;

    int zi = blk * 256 + t;
    if (zi < BN_) { g_rowsum[zi] = 0.f; g_colsum[zi] = 0.f; }

    __shared__ int sf;
    if (t == 0) sf = 0;
    __syncthreads();
    if (blk == 0) {
        int f = 0;
        for (int i = t; i < 4096; i += 256)
            if (m1[i] > 1u) f = 1;
        if (f) sf = 1;
    }
    __syncthreads();
    if (blk == 0 && t == 0) g_mask_u8 = sf;

    const float* W; bf16* Th; int N, tile;
    const int K = DN_;
    if (blk < 16)      { W = W1a; Th = g_w1at; N = 256; tile = blk; }
    else if (blk < 24) { W = W1b; Th = g_w1bt; N = 128; tile = blk - 16; }
    else if (blk < 40) { W = W2a; Th = g_w2at; N = 256; tile = blk - 24; }
    else               { W = W2b; Th = g_w2bt; N = 128; tile = blk - 40; }
    int tn = N / 64;
    int k0 = (tile / tn) * 64, n0 = (tile % tn) * 64;

    __shared__ float s[64][65];
#pragma unroll
    for (int i = 0; i < 16; i++) {
        int idx = t + i * 256;
        int r = idx >> 6, c = idx & 63;
        s[r][c] = W[(size_t)(k0 + r) * N + n0 + c];
    }
    __syncthreads();
#pragma unroll
    for (int i = 0; i < 16; i++) {
        int idx = t + i * 256;
        int n = idx >> 6, k = idx & 63;
        Th[(size_t)(n0 + n) * K + k0 + k] = __float2bfloat16(s[k][n]);
    }
}

// ---------------- aggregation: float4 row gather, 4 neighbor-groups (round-13 version) ----------------
__global__ void aggregate_kernel(const float* __restrict__ nf,
                                 const float* __restrict__ rel,
                                 const int* __restrict__ nb1, const int* __restrict__ rl1, const void* __restrict__ m1,
                                 const int* __restrict__ nb2, const int* __restrict__ rl2, const void* __restrict__ m2,
                                 const int* __restrict__ selfids) {
    int b = blockIdx.x;
    const int* nb; const int* rl; const void* m; bf16* oh;
    if (b < BN_) { nb = nb1; rl = rl1; m = m1; oh = g_v1; }
    else         { b -= BN_; nb = nb2; rl = rl2; m = m2; oh = g_v2; }

    __shared__ int s_nb[KN_];
    __shared__ float s_rcnt[16];
    __shared__ int s_cnt;
    __shared__ __align__(16) float s_part[4 * 256];
    int t = threadIdx.x;
    if (t < 16) s_rcnt[t] = 0.f;
    __syncthreads();
    if (t < KN_) {
        int mk;
        if (g_mask_u8) mk = ((const unsigned char*)m)[b * KN_ + t];
        else           mk = ((const int*)m)[b * KN_ + t];
        mk = (mk != 0);
        int nbv = nb[b * KN_ + t];
        int rlv = rl[b * KN_ + t];
        unsigned bal = __ballot_sync(0xFFFFFFFFu, mk);
        if (mk) {
            int pos = __popc(bal & ((1u << t) - 1u));
            s_nb[pos] = nbv;
            atomicAdd(&s_rcnt[rlv], 1.f);
        }
        if (t == 0) s_cnt = __popc(bal);
    }
    __syncthreads();
    int cnt = s_cnt;

    int g = t >> 6, l64 = t & 63;
    float4 a0 = make_float4(0.f, 0.f, 0.f, 0.f);
    float4 a1 = make_float4(0.f, 0.f, 0.f, 0.f);
    int k = g;
    for (; k + 4 < cnt; k += 8) {
        float4 v0 = *((const float4*)(nf + (size_t)s_nb[k] * DN_) + l64);
        float4 v1 = *((const float4*)(nf + (size_t)s_nb[k + 4] * DN_) + l64);
        a0.x += v0.x; a0.y += v0.y; a0.z += v0.z; a0.w += v0.w;
        a1.x += v1.x; a1.y += v1.y; a1.z += v1.z; a1.w += v1.w;
    }
    if (k < cnt) {
        float4 v0 = *((const float4*)(nf + (size_t)s_nb[k] * DN_) + l64);
        a0.x += v0.x; a0.y += v0.y; a0.z += v0.z; a0.w += v0.w;
    }
    a0.x += a1.x; a0.y += a1.y; a0.z += a1.z; a0.w += a1.w;
    ((float4*)s_part)[g * 64 + l64] = a0;
    __syncthreads();

    int d = t;
    float acc = s_part[d] + s_part[256 + d] + s_part[512 + d] + s_part[768 + d];
#pragma unroll
    for (int r = 0; r < NREL_; r++)
        acc = fmaf(s_rcnt[r], rel[r * DN_ + d], acc);
    float res;
    if (cnt > 0) res = acc / (float)cnt;
    else         res = nf[(size_t)selfids[b] * DN_ + d];
    oh[(size_t)b * DN_ + d] = __float2bfloat16(res);
}

// ---------------- fused proj: h = relu(v@Wa^T+ba); z = normalize(h@Wb^T+bb) ----------------
#define SV_OFF 0
#define SH_OFF 33792
#define SW0_OFF 67584
#define SW1_OFF 101376
#define FPROJ_SMEM 135168

__device__ __forceinline__ void load_rows64(uint32_t sdst, const bf16* gsrc, int tid) {
#pragma unroll
    for (int i = 0; i < 8; i++) {
        int e = tid + i * 256;
        int row = e >> 5, seg = e & 31;
        cp16(sdst + (uint32_t)(row * TSF + seg * 8) * 2, gsrc + (size_t)row * DN_ + seg * 8);
    }
}

__global__ void __launch_bounds__(256, 1) fused_proj_kernel(
        const float* __restrict__ b1a, const float* __restrict__ b2a,
        const float* __restrict__ b1b, const float* __restrict__ b2b) {
    extern __shared__ char smem_dyn[];
    __shared__ float s_ss[64];
    uint32_t sb = (uint32_t)__cvta_generic_to_shared(smem_dyn);
    uint32_t sV = sb + SV_OFF, sH = sb + SH_OFF;
    uint32_t sW[2] = { sb + SW0_OFF, sb + SW1_OFF };

    int tid = threadIdx.x;
    int lane = tid & 31, w = tid >> 5;
    int wr = w >> 1, wc = w & 1;
    int grp = lane >> 2, qp = (lane & 3) * 2;
    int bm = blockIdx.x * 64;
    int view = blockIdx.z;
    const bf16* V  = view ? g_v2 : g_v1;
    const bf16* Wa = view ? g_w2at : g_w1at;
    const bf16* Wb = view ? g_w2bt : g_w1bt;
    const float* ba = view ? b2a : b1a;
    const float* bb = view ? b2b : b1b;
    bf16* Z = view ? g_z2 : g_z1;

    if (tid < 64) s_ss[tid] = 0.f;

    int rowA = (lane & 7) + ((lane >> 3) & 1) * 8;
    int kA   = (lane >> 4) * 8;
    int rowB = (lane & 7) + (lane >> 4) * 8;
    int kB   = ((lane >> 3) & 1) * 8;

    load_rows64(sV, V + (size_t)bm * DN_, tid);
    load_rows64(sW[0], Wa, tid);
    cpcommit();

    float c2[2][4][4] = {};

    // -------- phase 1: h = relu(v @ Wa^T + ba) --------
#pragma unroll 1
    for (int c = 0; c < 4; c++) {
        cpwait<0>();
        __syncthreads();
        if (c < 3)      load_rows64(sW[(c + 1) & 1], Wa + (size_t)(c + 1) * 64 * DN_, tid);
        else            load_rows64(sW[(c + 1) & 1], Wb, tid);
        cpcommit();

        uint32_t sWc = sW[c & 1];
        float c1[4][4] = {};
#pragma unroll
        for (int kk = 0; kk < 256; kk += 16) {
            unsigned a[4];
            ldsm4(a, sV + (uint32_t)((wr * 16 + rowA) * TSF + kk + kA) * 2);
            unsigned bfrag[4][2];
#pragma unroll
            for (int np = 0; np < 2; np++) {
                unsigned r[4];
                ldsm4(r, sWc + (uint32_t)((wc * 32 + np * 16 + rowB) * TSF + kk + kB) * 2);
                bfrag[2 * np][0] = r[0]; bfrag[2 * np][1] = r[1];
                bfrag[2 * np + 1][0] = r[2]; bfrag[2 * np + 1][1] = r[3];
            }
#pragma unroll
            for (int ns = 0; ns < 4; ns++)
                mma16816(c1[ns], a[0], a[1], a[2], a[3], bfrag[ns][0], bfrag[ns][1]);
        }
#pragma unroll
        for (int ns = 0; ns < 4; ns++) {
            int col = c * 64 + wc * 32 + ns * 8 + qp;
            float bias0 = ba[col], bias1 = ba[col + 1];
#pragma unroll
            for (int h = 0; h < 2; h++) {
                int row = wr * 16 + grp + 8 * h;
                float v0 = fmaxf(c1[ns][2 * h + 0] + bias0, 0.f);
                float v1 = fmaxf(c1[ns][2 * h + 1] + bias1, 0.f);
                __nv_bfloat162 hp;
                hp.x = __float2bfloat16(v0); hp.y = __float2bfloat16(v1);
                *(__nv_bfloat162*)(smem_dyn + SH_OFF + (size_t)(row * TSF + col) * 2) = hp;
            }
        }
    }

    // -------- phase 2: z = h @ Wb^T + bb --------
#pragma unroll 1
    for (int c = 0; c < 2; c++) {
        cpwait<0>();
        __syncthreads();
        if (c < 1) { load_rows64(sW[(4 + c + 1) & 1], Wb + (size_t)64 * DN_, tid); cpcommit(); }

        uint32_t sWc = sW[(4 + c) & 1];
#pragma unroll
        for (int kk = 0; kk < 256; kk += 16) {
            unsigned a[4];
            ldsm4(a, sH + (uint32_t)((wr * 16 + rowA) * TSF + kk + kA) * 2);
            unsigned bfrag[4][2];
#pragma unroll
            for (int np = 0; np < 2; np++) {
                unsigned r[4];
                ldsm4(r, sWc + (uint32_t)((wc * 32 + np * 16 + rowB) * TSF + kk + kB) * 2);
                bfrag[2 * np][0] = r[0]; bfrag[2 * np][1] = r[1];
                bfrag[2 * np + 1][0] = r[2]; bfrag[2 * np + 1][1] = r[3];
            }
#pragma unroll
            for (int ns = 0; ns < 4; ns++)
                mma16816(c2[c][ns], a[0], a[1], a[2], a[3], bfrag[ns][0], bfrag[ns][1]);
        }
    }

    float vv[2][4][4];
#pragma unroll
    for (int c = 0; c < 2; c++)
#pragma unroll
        for (int ns = 0; ns < 4; ns++) {
            int col = c * 64 + wc * 32 + ns * 8 + qp;
            float bias0 = bb[col], bias1 = bb[col + 1];
#pragma unroll
            for (int h = 0; h < 2; h++) {
                vv[c][ns][2 * h + 0] = c2[c][ns][2 * h + 0] + bias0;
                vv[c][ns][2 * h + 1] = c2[c][ns][2 * h + 1] + bias1;
            }
        }
#pragma unroll
    for (int h = 0; h < 2; h++) {
        float ss = 0.f;
#pragma unroll
        for (int c = 0; c < 2; c++)
#pragma unroll
            for (int ns = 0; ns < 4; ns++) {
                float a = vv[c][ns][2 * h + 0], b = vv[c][ns][2 * h + 1];
                ss = fmaf(a, a, ss); ss = fmaf(b, b, ss);
            }
        ss += __shfl_xor_sync(0xFFFFFFFFu, ss, 1);
        ss += __shfl_xor_sync(0xFFFFFFFFu, ss, 2);
        if ((lane & 3) == 0)
            atomicAdd(&s_ss[wr * 16 + grp + 8 * h], ss);
    }
    __syncthreads();

#pragma unroll
    for (int h = 0; h < 2; h++) {
        int rloc = wr * 16 + grp + 8 * h;
        float rinv = rsqrtf(s_ss[rloc]);
        int row = bm + rloc;
#pragma unroll
        for (int c = 0; c < 2; c++)
#pragma unroll
            for (int ns = 0; ns < 4; ns++) {
                int col = c * 64 + wc * 32 + ns * 8 + qp;
                float v0 = vv[c][ns][2 * h + 0] * rinv;
                float v1 = vv[c][ns][2 * h + 1] * rinv;
                __nv_bfloat162 hp;
                hp.x = __float2bfloat16(v0); hp.y = __float2bfloat16(v1);
                *(__nv_bfloat162*)(Z + (size_t)row * DH_ + col) = hp;
            }
    }
}

// ---------------- sim: 2 bn-tiles per CTA, A reused, loads fully prefetched ----------------
__global__ void __launch_bounds__(256, 2) sim_lse_kernel() {
    extern __shared__ char smem_dyn[];
    __shared__ float s_rs[128], s_cs[2][128];
    int tid = threadIdx.x;
    int lane = tid & 31, w = tid >> 5;
    int wr = w >> 2, wc = w & 3;
    int grp = lane >> 2, qp = (lane & 3) * 2;
    int bm = blockIdx.x * 128, bn0 = blockIdx.y * 256;
    if (tid < 128) { s_rs[tid] = 0.f; s_cs[0][tid] = 0.f; s_cs[1][tid] = 0.f; }

    uint32_t sA = (uint32_t)__cvta_generic_to_shared(smem_dyn);
    uint32_t sB[2] = { sA + SIM_TILE_B, sA + 2 * SIM_TILE_B };

#pragma unroll
    for (int i = 0; i < 8; i++) {
        int idx = tid + i * 256;
        int row = idx >> 4, seg = idx & 15;
        uint32_t so = (uint32_t)(row * TSK + seg * 8) * 2;
        cp16(sA + so,    g_z1 + (size_t)(bm + row) * DH_ + seg * 8);
        cp16(sB[0] + so, g_z2 + (size_t)(bn0 + row) * DH_ + seg * 8);
    }
    cpcommit();
#pragma unroll
    for (int i = 0; i < 8; i++) {
        int idx = tid + i * 256;
        int row = idx >> 4, seg = idx & 15;
        cp16(sB[1] + (uint32_t)(row * TSK + seg * 8) * 2,
             g_z2 + (size_t)(bn0 + 128 + row) * DH_ + seg * 8);
    }
    cpcommit();

    int rowA = (lane & 7) + ((lane >> 3) & 1) * 8;
    int kA   = (lane >> 4) * 8;
    int rowB = (lane & 7) + (lane >> 4) * 8;
    int kB   = ((lane >> 3) & 1) * 8;

    float rs[4][2] = {};

#pragma unroll 1
    for (int j = 0; j < 2; j++) {
        if (j == 0) { cpwait<1>(); } else { cpwait<0>(); }
        __syncthreads();
        int bn = bn0 + j * 128;
        uint32_t sBj = sB[j];

        float c[4][4][4] = {};
#pragma unroll
        for (int kk = 0; kk < 128; kk += 16) {
            unsigned a[4][4];
#pragma unroll
            for (int ms = 0; ms < 4; ms++)
                ldsm4(a[ms], sA + (uint32_t)(((wr * 4 + ms) * 16 + rowA) * TSK + kk + kA) * 2);
            unsigned bfr[4][2];
#pragma unroll
            for (int np = 0; np < 2; np++) {
                unsigned r[4];
                ldsm4(r, sBj + (uint32_t)((wc * 32 + np * 16 + rowB) * TSK + kk + kB) * 2);
                bfr[2 * np][0] = r[0]; bfr[2 * np][1] = r[1];
                bfr[2 * np + 1][0] = r[2]; bfr[2 * np + 1][1] = r[3];
            }
#pragma unroll
            for (int ms = 0; ms < 4; ms++)
#pragma unroll
                for (int ns = 0; ns < 4; ns++)
                    mma16816(c[ms][ns], a[ms][0], a[ms][1], a[ms][2], a[ms][3], bfr[ns][0], bfr[ns][1]);
        }

        float cs[4][2] = {};
#pragma unroll
        for (int ms = 0; ms < 4; ms++) {
#pragma unroll
            for (int ns = 0; ns < 4; ns++) {
#pragma unroll
                for (int r = 0; r < 4; r++) {
                    int h = r >> 1, p = r & 1;
                    int row = bm + (wr * 4 + ms) * 16 + grp + 8 * h;
                    int col = bn + wc * 32 + ns * 8 + qp + p;
                    float s = c[ms][ns][r] * INV_T;
                    if (row == col) g_diag[row] = s;
                    float ev = __expf(s - INV_T);
                    rs[ms][h] += ev;
                    cs[ns][p] += ev;
                }
            }
        }
#pragma unroll
        for (int ns = 0; ns < 4; ns++)
#pragma unroll
            for (int p = 0; p < 2; p++) {
                float v = cs[ns][p];
                v += __shfl_xor_sync(0xFFFFFFFFu, v, 4);
                v += __shfl_xor_sync(0xFFFFFFFFu, v, 8);
                v += __shfl_xor_sync(0xFFFFFFFFu, v, 16);
                if (grp == 0)
                    atomicAdd(&s_cs[j][wc * 32 + ns * 8 + qp + p], v);
            }
    }

#pragma unroll
    for (int ms = 0; ms < 4; ms++)
#pragma unroll
        for (int h = 0; h < 2; h++) {
            float v = rs[ms][h];
            v += __shfl_xor_sync(0xFFFFFFFFu, v, 1);
            v += __shfl_xor_sync(0xFFFFFFFFu, v, 2);
            if ((lane & 3) == 0)
                atomicAdd(&s_rs[(wr * 4 + ms) * 16 + grp + 8 * h], v);
        }
    __syncthreads();
    if (tid < 128) {
        atomicAdd(&g_rowsum[bm + tid], s_rs[tid]);
        atomicAdd(&g_colsum[bn0 + tid], s_cs[0][tid]);
        atomicAdd(&g_colsum[bn0 + 128 + tid], s_cs[1][tid]);
    }
}

// ---------------- final loss reduce ----------------
__global__ void loss_kernel(float* __restrict__ out) {
    float acc = 0.f;
    for (int i = threadIdx.x; i < BN_; i += 256) {
        acc += 0.5f * (logf(g_rowsum[i]) + logf(g_colsum[i])) + INV_T - g_diag[i];
    }
#pragma unroll
    for (int off = 16; off; off >>= 1) acc += __shfl_xor_sync(0xFFFFFFFFu, acc, off);
    __shared__ float wsum[8];
    if ((threadIdx.x & 31) == 0) wsum[threadIdx.x >> 5] = acc;
    __syncthreads();
    if (threadIdx.x == 0) {
        float tot = 0.f;
        for (int k = 0; k < 8; k++) tot += wsum[k];
        out[0] = tot / (float)BN_;
    }
}

// ---------------- launch ----------------
extern "C" void kernel_launch(void* const* d_in, const int* in_sizes, int n_in,
                              void* d_out, int out_size) {
    const float* nf   = (const float*)d_in[0];
    const float* rel  = (const float*)d_in[1];
    const int*   nb1  = (const int*)d_in[2];
    const int*   rl1  = (const int*)d_in[3];
    const void*  m1   = d_in[4];
    const int*   nb2  = (const int*)d_in[5];
    const int*   rl2  = (const int*)d_in[6];
    const void*  m2   = d_in[7];
    const int*   self_ = (const int*)d_in[8];
    const float* W1a  = (const float*)d_in[9];
    const float* b1a  = (const float*)d_in[10];
    const float* W1b  = (const float*)d_in[11];
    const float* b1b  = (const float*)d_in[12];
    const float* W2a  = (const float*)d_in[13];
    const float* b2a  = (const float*)d_in[14];
    const float* W2b  = (const float*)d_in[15];
    const float* b2b  = (const float*)d_in[16];

    const int smemS = 3 * SIM_TILE_B;   // 104448
    cudaFuncSetAttribute(fused_proj_kernel, cudaFuncAttributeMaxDynamicSharedMemorySize, FPROJ_SMEM);
    cudaFuncSetAttribute(sim_lse_kernel,    cudaFuncAttributeMaxDynamicSharedMemorySize, smemS);

    prep_kernel<<<48, 256>>>(W1a, W1b, W2a, W2b, (const unsigned int*)m1);
    aggregate_kernel<<<2 * BN_, 256>>>(nf, rel, nb1, rl1, m1, nb2, rl2, m2, self_);
    fused_proj_kernel<<<dim3(64, 1, 2), 256, FPROJ_SMEM>>>(b1a, b2a, b1b, b2b);
    sim_lse_kernel<<<dim3(32, 16), 256, smemS>>>();
    loss_kernel<<<1, 256>>>((float*)d_out);
}

// round 16
// speedup vs baseline: 1.1548x; 1.0183x over previous
#include <cuda_runtime.h>
#include <cuda_bf16.h>
#include <math.h>
#include <stdint.h>

#define BN_ 4096
#define KN_ 32
#define DN_ 256
#define DH_ 128
#define NREL_ 9
#define INV_T 14.285714285714286f
#define K2E 20.609929217746826f   // INV_T * log2(e)
#define TSK 136  // sim smem stride (128 + 8 pad)
#define TSF 264  // fused-proj smem stride (256 + 8 pad)
#define SIM_TILE_B (128 * TSK * 2)

typedef __nv_bfloat16 bf16;

// ---------------- scratch ----------------
__device__ __align__(16) bf16 g_v1[BN_ * DN_];
__device__ __align__(16) bf16 g_v2[BN_ * DN_];
__device__ __align__(16) bf16 g_z1[BN_ * DH_];
__device__ __align__(16) bf16 g_z2[BN_ * DH_];
__device__ __align__(16) bf16 g_w1at[DN_ * DN_];
__device__ __align__(16) bf16 g_w1bt[DH_ * DN_];
__device__ __align__(16) bf16 g_w2at[DN_ * DN_];
__device__ __align__(16) bf16 g_w2bt[DH_ * DN_];
__device__ float g_rowsum[BN_];
__device__ float g_colsum[BN_];
__device__ float g_diag[BN_];
__device__ int   g_mask_u8;

// ---------------- async-copy / ldmatrix / mma primitives ----------------
__device__ __forceinline__ void cp16(uint32_t s, const void* g) {
    asm volatile("cp.async.cg.shared.global [%0], [%1], 16;\n" :: "r"(s), "l"(g));
}
__device__ __forceinline__ void cpcommit() {
    asm volatile("cp.async.commit_group;\n" ::: "memory");
}
template <int N>
__device__ __forceinline__ void cpwait() {
    asm volatile("cp.async.wait_group %0;\n" :: "n"(N) : "memory");
}
__device__ __forceinline__ void ldsm4(unsigned r[4], uint32_t a) {
    asm volatile("ldmatrix.sync.aligned.m8n8.x4.shared.b16 {%0,%1,%2,%3}, [%4];\n"
                 : "=r"(r[0]), "=r"(r[1]), "=r"(r[2]), "=r"(r[3]) : "r"(a));
}
__device__ __forceinline__ void mma16816(float c[4], unsigned a0, unsigned a1, unsigned a2, unsigned a3,
                                         unsigned b0, unsigned b1) {
    asm volatile("mma.sync.aligned.m16n8k16.row.col.f32.bf16.bf16.f32 "
                 "{%0,%1,%2,%3}, {%4,%5,%6,%7}, {%8,%9}, {%0,%1,%2,%3};\n"
                 : "+f"(c[0]), "+f"(c[1]), "+f"(c[2]), "+f"(c[3])
                 : "r"(a0), "r"(a1), "r"(a2), "r"(a3), "r"(b0), "r"(b1));
}
__device__ __forceinline__ float ex2f(float x) {
    float r;
    asm("ex2.approx.ftz.f32 %0, %1;" : "=f"(r) : "f"(x));
    return r;
}

// ---------------- prep: mask detect + zero + tiled weight transpose (bf16) ----------------
__global__ void prep_kernel(const float* __restrict__ W1a, const float* __restrict__ W1b,
                            const float* __restrict__ W2a, const float* __restrict__ W2b,
                            const unsigned int* __restrict__ m1) {
    int blk = blockIdx.x;
    int t = threadIdx.x;

    int zi = blk * 256 + t;
    if (zi < BN_) { g_rowsum[zi] = 0.f; g_colsum[zi] = 0.f; }

    __shared__ int sf;
    if (t == 0) sf = 0;
    __syncthreads();
    if (blk == 0) {
        int f = 0;
        for (int i = t; i < 4096; i += 256)
            if (m1[i] > 1u) f = 1;
        if (f) sf = 1;
    }
    __syncthreads();
    if (blk == 0 && t == 0) g_mask_u8 = sf;

    const float* W; bf16* Th; int N, tile;
    const int K = DN_;
    if (blk < 16)      { W = W1a; Th = g_w1at; N = 256; tile = blk; }
    else if (blk < 24) { W = W1b; Th = g_w1bt; N = 128; tile = blk - 16; }
    else if (blk < 40) { W = W2a; Th = g_w2at; N = 256; tile = blk - 24; }
    else               { W = W2b; Th = g_w2bt; N = 128; tile = blk - 40; }
    int tn = N / 64;
    int k0 = (tile / tn) * 64, n0 = (tile % tn) * 64;

    __shared__ float s[64][65];
#pragma unroll
    for (int i = 0; i < 16; i++) {
        int idx = t + i * 256;
        int r = idx >> 6, c = idx & 63;
        s[r][c] = W[(size_t)(k0 + r) * N + n0 + c];
    }
    __syncthreads();
#pragma unroll
    for (int i = 0; i < 16; i++) {
        int idx = t + i * 256;
        int n = idx >> 6, k = idx & 63;
        Th[(size_t)(n0 + n) * K + k0 + k] = __float2bfloat16(s[k][n]);
    }
}

// ---------------- aggregation: warp-per-node (no syncs, no smem) ----------------
// grid 1024 x 256 threads: 8 warps/block, warp w owns node blockIdx.x*8+w (0..8191).
__global__ void __launch_bounds__(256) aggregate_kernel(
        const float* __restrict__ nf, const float* __restrict__ rel,
        const int* __restrict__ nb1, const int* __restrict__ rl1, const void* __restrict__ m1,
        const int* __restrict__ nb2, const int* __restrict__ rl2, const void* __restrict__ m2,
        const int* __restrict__ selfids) {
    int b = blockIdx.x * 8 + (threadIdx.x >> 5);
    int lane = threadIdx.x & 31;
    const int* nb; const int* rl; const void* m; bf16* oh;
    if (b < BN_) { nb = nb1; rl = rl1; m = m1; oh = g_v1; }
    else         { b -= BN_; nb = nb2; rl = rl2; m = m2; oh = g_v2; }

    int mk;
    if (g_mask_u8) mk = ((const unsigned char*)m)[b * KN_ + lane];
    else           mk = ((const int*)m)[b * KN_ + lane];
    mk = (mk != 0);
    int nbv = nb[b * KN_ + lane];
    int rlv = rl[b * KN_ + lane];
    unsigned bal = __ballot_sync(0xFFFFFFFFu, mk);
    int cnt = __popc(bal);

    float acc[8] = {0.f, 0.f, 0.f, 0.f, 0.f, 0.f, 0.f, 0.f};

    // relation contribution via per-relation ballots (rel rows are L1-hot)
#pragma unroll
    for (int r = 0; r < NREL_; r++) {
        unsigned br = __ballot_sync(0xFFFFFFFFu, mk && (rlv == r));
        float cr = (float)__popc(br);
        if (br) {
            const float4* rp = (const float4*)(rel + r * DN_) + lane * 2;
            float4 r0 = rp[0], r1 = rp[1];
            acc[0] = fmaf(cr, r0.x, acc[0]); acc[1] = fmaf(cr, r0.y, acc[1]);
            acc[2] = fmaf(cr, r0.z, acc[2]); acc[3] = fmaf(cr, r0.w, acc[3]);
            acc[4] = fmaf(cr, r1.x, acc[4]); acc[5] = fmaf(cr, r1.y, acc[5]);
            acc[6] = fmaf(cr, r1.z, acc[6]); acc[7] = fmaf(cr, r1.w, acc[7]);
        }
    }

    // neighbor gather: lane owns dims [lane*8, lane*8+8)
    for (int k = 0; k < cnt; k++) {
        int src = __fns(bal, 0, k + 1);
        int nbk = __shfl_sync(0xFFFFFFFFu, nbv, src);
        const float4* p = (const float4*)(nf + (size_t)nbk * DN_) + lane * 2;
        float4 x0 = p[0], x1 = p[1];
        acc[0] += x0.x; acc[1] += x0.y; acc[2] += x0.z; acc[3] += x0.w;
        acc[4] += x1.x; acc[5] += x1.y; acc[6] += x1.z; acc[7] += x1.w;
    }

    if (cnt > 0) {
        float inv = 1.f / (float)cnt;
#pragma unroll
        for (int j = 0; j < 8; j++) acc[j] *= inv;
    } else {
        const float4* p = (const float4*)(nf + (size_t)selfids[b] * DN_) + lane * 2;
        float4 x0 = p[0], x1 = p[1];
        acc[0] = x0.x; acc[1] = x0.y; acc[2] = x0.z; acc[3] = x0.w;
        acc[4] = x1.x; acc[5] = x1.y; acc[6] = x1.z; acc[7] = x1.w;
    }

    __nv_bfloat162 o[4];
#pragma unroll
    for (int j = 0; j < 4; j++) {
        o[j].x = __float2bfloat16(acc[2 * j]);
        o[j].y = __float2bfloat16(acc[2 * j + 1]);
    }
    *(uint4*)(oh + (size_t)b * DN_ + lane * 8) = *(uint4*)o;
}

// ---------------- fused proj: h = relu(v@Wa^T+ba); z = normalize(h@Wb^T+bb) ----------------
#define SV_OFF 0
#define SH_OFF 33792
#define SW0_OFF 67584
#define SW1_OFF 101376
#define FPROJ_SMEM 135168

__device__ __forceinline__ void load_rows64(uint32_t sdst, const bf16* gsrc, int tid) {
#pragma unroll
    for (int i = 0; i < 8; i++) {
        int e = tid + i * 256;
        int row = e >> 5, seg = e & 31;
        cp16(sdst + (uint32_t)(row * TSF + seg * 8) * 2, gsrc + (size_t)row * DN_ + seg * 8);
    }
}

__global__ void __launch_bounds__(256, 1) fused_proj_kernel(
        const float* __restrict__ b1a, const float* __restrict__ b2a,
        const float* __restrict__ b1b, const float* __restrict__ b2b) {
    extern __shared__ char smem_dyn[];
    __shared__ float s_ss[64];
    uint32_t sb = (uint32_t)__cvta_generic_to_shared(smem_dyn);
    uint32_t sV = sb + SV_OFF, sH = sb + SH_OFF;
    uint32_t sW[2] = { sb + SW0_OFF, sb + SW1_OFF };

    int tid = threadIdx.x;
    int lane = tid & 31, w = tid >> 5;
    int wr = w >> 1, wc = w & 1;
    int grp = lane >> 2, qp = (lane & 3) * 2;
    int bm = blockIdx.x * 64;
    int view = blockIdx.z;
    const bf16* V  = view ? g_v2 : g_v1;
    const bf16* Wa = view ? g_w2at : g_w1at;
    const bf16* Wb = view ? g_w2bt : g_w1bt;
    const float* ba = view ? b2a : b1a;
    const float* bb = view ? b2b : b1b;
    bf16* Z = view ? g_z2 : g_z1;

    if (tid < 64) s_ss[tid] = 0.f;

    int rowA = (lane & 7) + ((lane >> 3) & 1) * 8;
    int kA   = (lane >> 4) * 8;
    int rowB = (lane & 7) + (lane >> 4) * 8;
    int kB   = ((lane >> 3) & 1) * 8;

    load_rows64(sV, V + (size_t)bm * DN_, tid);
    load_rows64(sW[0], Wa, tid);
    cpcommit();

    float c2[2][4][4] = {};

    // -------- phase 1: h = relu(v @ Wa^T + ba) --------
#pragma unroll 1
    for (int c = 0; c < 4; c++) {
        cpwait<0>();
        __syncthreads();
        if (c < 3)      load_rows64(sW[(c + 1) & 1], Wa + (size_t)(c + 1) * 64 * DN_, tid);
        else            load_rows64(sW[(c + 1) & 1], Wb, tid);
        cpcommit();

        uint32_t sWc = sW[c & 1];
        float c1[4][4] = {};
#pragma unroll
        for (int kk = 0; kk < 256; kk += 16) {
            unsigned a[4];
            ldsm4(a, sV + (uint32_t)((wr * 16 + rowA) * TSF + kk + kA) * 2);
            unsigned bfrag[4][2];
#pragma unroll
            for (int np = 0; np < 2; np++) {
                unsigned r[4];
                ldsm4(r, sWc + (uint32_t)((wc * 32 + np * 16 + rowB) * TSF + kk + kB) * 2);
                bfrag[2 * np][0] = r[0]; bfrag[2 * np][1] = r[1];
                bfrag[2 * np + 1][0] = r[2]; bfrag[2 * np + 1][1] = r[3];
            }
#pragma unroll
            for (int ns = 0; ns < 4; ns++)
                mma16816(c1[ns], a[0], a[1], a[2], a[3], bfrag[ns][0], bfrag[ns][1]);
        }
#pragma unroll
        for (int ns = 0; ns < 4; ns++) {
            int col = c * 64 + wc * 32 + ns * 8 + qp;
            float bias0 = ba[col], bias1 = ba[col + 1];
#pragma unroll
            for (int h = 0; h < 2; h++) {
                int row = wr * 16 + grp + 8 * h;
                float v0 = fmaxf(c1[ns][2 * h + 0] + bias0, 0.f);
                float v1 = fmaxf(c1[ns][2 * h + 1] + bias1, 0.f);
                __nv_bfloat162 hp;
                hp.x = __float2bfloat16(v0); hp.y = __float2bfloat16(v1);
                *(__nv_bfloat162*)(smem_dyn + SH_OFF + (size_t)(row * TSF + col) * 2) = hp;
            }
        }
    }

    // -------- phase 2: z = h @ Wb^T + bb --------
#pragma unroll 1
    for (int c = 0; c < 2; c++) {
        cpwait<0>();
        __syncthreads();
        if (c < 1) { load_rows64(sW[(4 + c + 1) & 1], Wb + (size_t)64 * DN_, tid); cpcommit(); }

        uint32_t sWc = sW[(4 + c) & 1];
#pragma unroll
        for (int kk = 0; kk < 256; kk += 16) {
            unsigned a[4];
            ldsm4(a, sH + (uint32_t)((wr * 16 + rowA) * TSF + kk + kA) * 2);
            unsigned bfrag[4][2];
#pragma unroll
            for (int np = 0; np < 2; np++) {
                unsigned r[4];
                ldsm4(r, sWc + (uint32_t)((wc * 32 + np * 16 + rowB) * TSF + kk + kB) * 2);
                bfrag[2 * np][0] = r[0]; bfrag[2 * np][1] = r[1];
                bfrag[2 * np + 1][0] = r[2]; bfrag[2 * np + 1][1] = r[3];
            }
#pragma unroll
            for (int ns = 0; ns < 4; ns++)
                mma16816(c2[c][ns], a[0], a[1], a[2], a[3], bfrag[ns][0], bfrag[ns][1]);
        }
    }

    float vv[2][4][4];
#pragma unroll
    for (int c = 0; c < 2; c++)
#pragma unroll
        for (int ns = 0; ns < 4; ns++) {
            int col = c * 64 + wc * 32 + ns * 8 + qp;
            float bias0 = bb[col], bias1 = bb[col + 1];
#pragma unroll
            for (int h = 0; h < 2; h++) {
                vv[c][ns][2 * h + 0] = c2[c][ns][2 * h + 0] + bias0;
                vv[c][ns][2 * h + 1] = c2[c][ns][2 * h + 1] + bias1;
            }
        }
#pragma unroll
    for (int h = 0; h < 2; h++) {
        float ss = 0.f;
#pragma unroll
        for (int c = 0; c < 2; c++)
#pragma unroll
            for (int ns = 0; ns < 4; ns++) {
                float a = vv[c][ns][2 * h + 0], b = vv[c][ns][2 * h + 1];
                ss = fmaf(a, a, ss); ss = fmaf(b, b, ss);
            }
        ss += __shfl_xor_sync(0xFFFFFFFFu, ss, 1);
        ss += __shfl_xor_sync(0xFFFFFFFFu, ss, 2);
        if ((lane & 3) == 0)
            atomicAdd(&s_ss[wr * 16 + grp + 8 * h], ss);
    }
    __syncthreads();

#pragma unroll
    for (int h = 0; h < 2; h++) {
        int rloc = wr * 16 + grp + 8 * h;
        float rinv = rsqrtf(s_ss[rloc]);
        int row = bm + rloc;
#pragma unroll
        for (int c = 0; c < 2; c++)
#pragma unroll
            for (int ns = 0; ns < 4; ns++) {
                int col = c * 64 + wc * 32 + ns * 8 + qp;
                float v0 = vv[c][ns][2 * h + 0] * rinv;
                float v1 = vv[c][ns][2 * h + 1] * rinv;
                __nv_bfloat162 hp;
                hp.x = __float2bfloat16(v0); hp.y = __float2bfloat16(v1);
                *(__nv_bfloat162*)(Z + (size_t)row * DH_ + col) = hp;
            }
    }
}

// ---------------- sim: 2 bn-tiles per CTA, tile-level diag, fused ex2 epilogue ----------------
__global__ void __launch_bounds__(256, 2) sim_lse_kernel() {
    extern __shared__ char smem_dyn[];
    __shared__ float s_rs[128], s_cs[2][128];
    int tid = threadIdx.x;
    int lane = tid & 31, w = tid >> 5;
    int wr = w >> 2, wc = w & 3;
    int grp = lane >> 2, qp = (lane & 3) * 2;
    int bm = blockIdx.x * 128, bn0 = blockIdx.y * 256;
    if (tid < 128) { s_rs[tid] = 0.f; s_cs[0][tid] = 0.f; s_cs[1][tid] = 0.f; }

    uint32_t sA = (uint32_t)__cvta_generic_to_shared(smem_dyn);
    uint32_t sB[2] = { sA + SIM_TILE_B, sA + 2 * SIM_TILE_B };

#pragma unroll
    for (int i = 0; i < 8; i++) {
        int idx = tid + i * 256;
        int row = idx >> 4, seg = idx & 15;
        uint32_t so = (uint32_t)(row * TSK + seg * 8) * 2;
        cp16(sA + so,    g_z1 + (size_t)(bm + row) * DH_ + seg * 8);
        cp16(sB[0] + so, g_z2 + (size_t)(bn0 + row) * DH_ + seg * 8);
    }
    cpcommit();
#pragma unroll
    for (int i = 0; i < 8; i++) {
        int idx = tid + i * 256;
        int row = idx >> 4, seg = idx & 15;
        cp16(sB[1] + (uint32_t)(row * TSK + seg * 8) * 2,
             g_z2 + (size_t)(bn0 + 128 + row) * DH_ + seg * 8);
    }
    cpcommit();

    int rowA = (lane & 7) + ((lane >> 3) & 1) * 8;
    int kA   = (lane >> 4) * 8;
    int rowB = (lane & 7) + (lane >> 4) * 8;
    int kB   = ((lane >> 3) & 1) * 8;

    float rs[4][2] = {};

#pragma unroll 1
    for (int j = 0; j < 2; j++) {
        if (j == 0) { cpwait<1>(); } else { cpwait<0>(); }
        __syncthreads();
        int bn = bn0 + j * 128;
        uint32_t sBj = sB[j];
        bool diag_tile = (bm == bn);

        float c[4][4][4] = {};
#pragma unroll
        for (int kk = 0; kk < 128; kk += 16) {
            unsigned a[4][4];
#pragma unroll
            for (int ms = 0; ms < 4; ms++)
                ldsm4(a[ms], sA + (uint32_t)(((wr * 4 + ms) * 16 + rowA) * TSK + kk + kA) * 2);
            unsigned bfr[4][2];
#pragma unroll
            for (int np = 0; np < 2; np++) {
                unsigned r[4];
                ldsm4(r, sBj + (uint32_t)((wc * 32 + np * 16 + rowB) * TSK + kk + kB) * 2);
                bfr[2 * np][0] = r[0]; bfr[2 * np][1] = r[1];
                bfr[2 * np + 1][0] = r[2]; bfr[2 * np + 1][1] = r[3];
            }
#pragma unroll
            for (int ms = 0; ms < 4; ms++)
#pragma unroll
                for (int ns = 0; ns < 4; ns++)
                    mma16816(c[ms][ns], a[ms][0], a[ms][1], a[ms][2], a[ms][3], bfr[ns][0], bfr[ns][1]);
        }

        // diag extraction only for the 1-in-16 diagonal tiles
        if (diag_tile) {
#pragma unroll
            for (int ms = 0; ms < 4; ms++)
#pragma unroll
                for (int ns = 0; ns < 4; ns++)
#pragma unroll
                    for (int r = 0; r < 4; r++) {
                        int h = r >> 1, p = r & 1;
                        int rloc = (wr * 4 + ms) * 16 + grp + 8 * h;
                        int cloc = wc * 32 + ns * 8 + qp + p;
                        if (rloc == cloc) g_diag[bm + rloc] = c[ms][ns][r] * INV_T;
                    }
        }

        float cs[4][2] = {};
#pragma unroll
        for (int ms = 0; ms < 4; ms++) {
#pragma unroll
            for (int ns = 0; ns < 4; ns++) {
#pragma unroll
                for (int r = 0; r < 4; r++) {
                    int h = r >> 1, p = r & 1;
                    float ev = ex2f(fmaf(c[ms][ns][r], K2E, -K2E));
                    rs[ms][h] += ev;
                    cs[ns][p] += ev;
                }
            }
        }
#pragma unroll
        for (int ns = 0; ns < 4; ns++)
#pragma unroll
            for (int p = 0; p < 2; p++) {
                float v = cs[ns][p];
                v += __shfl_xor_sync(0xFFFFFFFFu, v, 4);
                v += __shfl_xor_sync(0xFFFFFFFFu, v, 8);
                v += __shfl_xor_sync(0xFFFFFFFFu, v, 16);
                if (grp == 0)
                    atomicAdd(&s_cs[j][wc * 32 + ns * 8 + qp + p], v);
            }
    }

#pragma unroll
    for (int ms = 0; ms < 4; ms++)
#pragma unroll
        for (int h = 0; h < 2; h++) {
            float v = rs[ms][h];
            v += __shfl_xor_sync(0xFFFFFFFFu, v, 1);
            v += __shfl_xor_sync(0xFFFFFFFFu, v, 2);
            if ((lane & 3) == 0)
                atomicAdd(&s_rs[(wr * 4 + ms) * 16 + grp + 8 * h], v);
        }
    __syncthreads();
    if (tid < 128) {
        atomicAdd(&g_rowsum[bm + tid], s_rs[tid]);
        atomicAdd(&g_colsum[bn0 + tid], s_cs[0][tid]);
        atomicAdd(&g_colsum[bn0 + 128 + tid], s_cs[1][tid]);
    }
}

// ---------------- final loss reduce ----------------
__global__ void loss_kernel(float* __restrict__ out) {
    float acc = 0.f;
    for (int i = threadIdx.x; i < BN_; i += 256) {
        acc += 0.5f * (logf(g_rowsum[i]) + logf(g_colsum[i])) + INV_T - g_diag[i];
    }
#pragma unroll
    for (int off = 16; off; off >>= 1) acc += __shfl_xor_sync(0xFFFFFFFFu, acc, off);
    __shared__ float wsum[8];
    if ((threadIdx.x & 31) == 0) wsum[threadIdx.x >> 5] = acc;
    __syncthreads();
    if (threadIdx.x == 0) {
        float tot = 0.f;
        for (int k = 0; k < 8; k++) tot += wsum[k];
        out[0] = tot / (float)BN_;
    }
}

// ---------------- launch ----------------
extern "C" void kernel_launch(void* const* d_in, const int* in_sizes, int n_in,
                              void* d_out, int out_size) {
    const float* nf   = (const float*)d_in[0];
    const float* rel  = (const float*)d_in[1];
    const int*   nb1  = (const int*)d_in[2];
    const int*   rl1  = (const int*)d_in[3];
    const void*  m1   = d_in[4];
    const int*   nb2  = (const int*)d_in[5];
    const int*   rl2  = (const int*)d_in[6];
    const void*  m2   = d_in[7];
    const int*   self_ = (const int*)d_in[8];
    const float* W1a  = (const float*)d_in[9];
    const float* b1a  = (const float*)d_in[10];
    const float* W1b  = (const float*)d_in[11];
    const float* b1b  = (const float*)d_in[12];
    const float* W2a  = (const float*)d_in[13];
    const float* b2a  = (const float*)d_in[14];
    const float* W2b  = (const float*)d_in[15];
    const float* b2b  = (const float*)d_in[16];

    const int smemS = 3 * SIM_TILE_B;   // 104448
    cudaFuncSetAttribute(fused_proj_kernel, cudaFuncAttributeMaxDynamicSharedMemorySize, FPROJ_SMEM);
    cudaFuncSetAttribute(sim_lse_kernel,    cudaFuncAttributeMaxDynamicSharedMemorySize, smemS);

    prep_kernel<<<48, 256>>>(W1a, W1b, W2a, W2b, (const unsigned int*)m1);
    aggregate_kernel<<<1024, 256>>>(nf, rel, nb1, rl1, m1, nb2, rl2, m2, self_);
    fused_proj_kernel<<<dim3(64, 1, 2), 256, FPROJ_SMEM>>>(b1a, b2a, b1b, b2b);
    sim_lse_kernel<<<dim3(32, 16), 256, smemS>>>();
    loss_kernel<<<1, 256>>>((float*)d_out);
}

// round 17
// speedup vs baseline: 1.2619x; 1.0928x over previous
#include <cuda_runtime.h>
#include <cuda_bf16.h>
#include <math.h>
#include <stdint.h>

#define BN_ 4096
#define KN_ 32
#define DN_ 256
#define DH_ 128
#define NREL_ 9
#define INV_T 14.285714285714286f
#define K2E 20.609929217746826f   // INV_T * log2(e)
#define TSK 136
#define TSF 264
#define SIM_TILE_B (128 * TSK * 2)

typedef __nv_bfloat16 bf16;

// ---------------- scratch ----------------
__device__ __align__(16) bf16 g_v1[BN_ * DN_];
__device__ __align__(16) bf16 g_v2[BN_ * DN_];
__device__ __align__(16) bf16 g_z1[BN_ * DH_];
__device__ __align__(16) bf16 g_z2[BN_ * DH_];
__device__ __align__(16) bf16 g_w1at[DN_ * DN_];
__device__ __align__(16) bf16 g_w1bt[DH_ * DN_];
__device__ __align__(16) bf16 g_w2at[DN_ * DN_];
__device__ __align__(16) bf16 g_w2bt[DH_ * DN_];
__device__ float g_rowsum[BN_];
__device__ float g_colsum[BN_];
__device__ float g_diag[BN_];
__device__ int   g_mask_u8;

// ---------------- primitives ----------------
__device__ __forceinline__ void cp16(uint32_t s, const void* g) {
    asm volatile("cp.async.cg.shared.global [%0], [%1], 16;\n" :: "r"(s), "l"(g));
}
__device__ __forceinline__ void cpcommit() {
    asm volatile("cp.async.commit_group;\n" ::: "memory");
}
template <int N>
__device__ __forceinline__ void cpwait() {
    asm volatile("cp.async.wait_group %0;\n" :: "n"(N) : "memory");
}
__device__ __forceinline__ void ldsm4(unsigned r[4], uint32_t a) {
    asm volatile("ldmatrix.sync.aligned.m8n8.x4.shared.b16 {%0,%1,%2,%3}, [%4];\n"
                 : "=r"(r[0]), "=r"(r[1]), "=r"(r[2]), "=r"(r[3]) : "r"(a));
}
__device__ __forceinline__ void mma16816(float c[4], unsigned a0, unsigned a1, unsigned a2, unsigned a3,
                                         unsigned b0, unsigned b1) {
    asm volatile("mma.sync.aligned.m16n8k16.row.col.f32.bf16.bf16.f32 "
                 "{%0,%1,%2,%3}, {%4,%5,%6,%7}, {%8,%9}, {%0,%1,%2,%3};\n"
                 : "+f"(c[0]), "+f"(c[1]), "+f"(c[2]), "+f"(c[3])
                 : "r"(a0), "r"(a1), "r"(a2), "r"(a3), "r"(b0), "r"(b1));
}
__device__ __forceinline__ float ex2f(float x) {
    float r;
    asm("ex2.approx.ftz.f32 %0, %1;" : "=f"(r) : "f"(x));
    return r;
}

// ---------------- detect: mask dtype (writes g_mask_u8) ----------------
__global__ void detect_kernel(const unsigned int* __restrict__ m1) {
    __shared__ int sf;
    if (threadIdx.x == 0) sf = 0;
    __syncthreads();
    int f = 0;
    for (int i = threadIdx.x; i < 4096; i += 256)
        if (m1[i] > 1u) f = 1;
    if (f) sf = 1;
    __syncthreads();
    if (threadIdx.x == 0) g_mask_u8 = sf;
}

// ---------------- merged prep (blocks 0..47) + aggregate (blocks 48..1071) ----------------
__global__ void __launch_bounds__(256) agg_prep_kernel(
        const float* __restrict__ nf, const float* __restrict__ rel,
        const int* __restrict__ nb1, const int* __restrict__ rl1, const void* __restrict__ m1,
        const int* __restrict__ nb2, const int* __restrict__ rl2, const void* __restrict__ m2,
        const int* __restrict__ selfids,
        const float* __restrict__ W1a, const float* __restrict__ W1b,
        const float* __restrict__ W2a, const float* __restrict__ W2b) {
    int blk = blockIdx.x;
    int t = threadIdx.x;

    if (blk < 48) {
        // ---- prep: zero accumulators + tiled weight transpose ----
        int zi = blk * 256 + t;
        if (zi < BN_) { g_rowsum[zi] = 0.f; g_colsum[zi] = 0.f; }

        const float* W; bf16* Th; int N, tile;
        const int K = DN_;
        if (blk < 16)      { W = W1a; Th = g_w1at; N = 256; tile = blk; }
        else if (blk < 24) { W = W1b; Th = g_w1bt; N = 128; tile = blk - 16; }
        else if (blk < 40) { W = W2a; Th = g_w2at; N = 256; tile = blk - 24; }
        else               { W = W2b; Th = g_w2bt; N = 128; tile = blk - 40; }
        int tn = N / 64;
        int k0 = (tile / tn) * 64, n0 = (tile % tn) * 64;

        __shared__ float s[64][65];
#pragma unroll
        for (int i = 0; i < 16; i++) {
            int idx = t + i * 256;
            int r = idx >> 6, c = idx & 63;
            s[r][c] = W[(size_t)(k0 + r) * N + n0 + c];
        }
        __syncthreads();
#pragma unroll
        for (int i = 0; i < 16; i++) {
            int idx = t + i * 256;
            int n = idx >> 6, k = idx & 63;
            Th[(size_t)(n0 + n) * K + k0 + k] = __float2bfloat16(s[k][n]);
        }
        return;
    }

    // ---- aggregate: warp-per-node, register-compacted list, 4x-unrolled gather ----
    int b = (blk - 48) * 8 + (t >> 5);
    int lane = t & 31;
    const int* nb; const int* rl; const void* m; bf16* oh;
    if (b < BN_) { nb = nb1; rl = rl1; m = m1; oh = g_v1; }
    else         { b -= BN_; nb = nb2; rl = rl2; m = m2; oh = g_v2; }

    int mk;
    if (g_mask_u8) mk = ((const unsigned char*)m)[b * KN_ + lane];
    else           mk = ((const int*)m)[b * KN_ + lane];
    mk = (mk != 0);
    int nbv = nb[b * KN_ + lane];
    int rlv = rl[b * KN_ + lane];
    unsigned bal = __ballot_sync(0xFFFFFFFFu, mk);
    int cnt = __popc(bal);

    // compacted neighbor list in registers: lane l holds the l-th masked neighbor id
    unsigned src = __fns(bal, 0, lane + 1);
    if (src > 31u) src = 0u;
    int nbl = __shfl_sync(0xFFFFFFFFu, nbv, src);

    float acc[8] = {0.f, 0.f, 0.f, 0.f, 0.f, 0.f, 0.f, 0.f};

    // relation contribution via per-relation ballots
#pragma unroll
    for (int r = 0; r < NREL_; r++) {
        unsigned br = __ballot_sync(0xFFFFFFFFu, mk && (rlv == r));
        float cr = (float)__popc(br);
        if (br) {
            const float4* rp = (const float4*)(rel + r * DN_) + lane * 2;
            float4 r0 = rp[0], r1 = rp[1];
            acc[0] = fmaf(cr, r0.x, acc[0]); acc[1] = fmaf(cr, r0.y, acc[1]);
            acc[2] = fmaf(cr, r0.z, acc[2]); acc[3] = fmaf(cr, r0.w, acc[3]);
            acc[4] = fmaf(cr, r1.x, acc[4]); acc[5] = fmaf(cr, r1.y, acc[5]);
            acc[6] = fmaf(cr, r1.z, acc[6]); acc[7] = fmaf(cr, r1.w, acc[7]);
        }
    }

    // gather: 4 neighbors / iteration -> 8 independent 16B loads in flight
    int k = 0;
    for (; k + 3 < cnt; k += 4) {
        int n0 = __shfl_sync(0xFFFFFFFFu, nbl, k);
        int n1 = __shfl_sync(0xFFFFFFFFu, nbl, k + 1);
        int n2 = __shfl_sync(0xFFFFFFFFu, nbl, k + 2);
        int n3 = __shfl_sync(0xFFFFFFFFu, nbl, k + 3);
        const float4* p0 = (const float4*)(nf + (size_t)n0 * DN_) + lane * 2;
        const float4* p1 = (const float4*)(nf + (size_t)n1 * DN_) + lane * 2;
        const float4* p2 = (const float4*)(nf + (size_t)n2 * DN_) + lane * 2;
        const float4* p3 = (const float4*)(nf + (size_t)n3 * DN_) + lane * 2;
        float4 x00 = p0[0], x01 = p0[1];
        float4 x10 = p1[0], x11 = p1[1];
        float4 x20 = p2[0], x21 = p2[1];
        float4 x30 = p3[0], x31 = p3[1];
        acc[0] += (x00.x + x10.x) + (x20.x + x30.x);
        acc[1] += (x00.y + x10.y) + (x20.y + x30.y);
        acc[2] += (x00.z + x10.z) + (x20.z + x30.z);
        acc[3] += (x00.w + x10.w) + (x20.w + x30.w);
        acc[4] += (x01.x + x11.x) + (x21.x + x31.x);
        acc[5] += (x01.y + x11.y) + (x21.y + x31.y);
        acc[6] += (x01.z + x11.z) + (x21.z + x31.z);
        acc[7] += (x01.w + x11.w) + (x21.w + x31.w);
    }
    for (; k < cnt; k++) {
        int n0 = __shfl_sync(0xFFFFFFFFu, nbl, k);
        const float4* p = (const float4*)(nf + (size_t)n0 * DN_) + lane * 2;
        float4 x0 = p[0], x1 = p[1];
        acc[0] += x0.x; acc[1] += x0.y; acc[2] += x0.z; acc[3] += x0.w;
        acc[4] += x1.x; acc[5] += x1.y; acc[6] += x1.z; acc[7] += x1.w;
    }

    if (cnt > 0) {
        float inv = 1.f / (float)cnt;
#pragma unroll
        for (int j = 0; j < 8; j++) acc[j] *= inv;
    } else {
        const float4* p = (const float4*)(nf + (size_t)selfids[b] * DN_) + lane * 2;
        float4 x0 = p[0], x1 = p[1];
        acc[0] = x0.x; acc[1] = x0.y; acc[2] = x0.z; acc[3] = x0.w;
        acc[4] = x1.x; acc[5] = x1.y; acc[6] = x1.z; acc[7] = x1.w;
    }

    __nv_bfloat162 o[4];
#pragma unroll
    for (int j = 0; j < 4; j++) {
        o[j].x = __float2bfloat16(acc[2 * j]);
        o[j].y = __float2bfloat16(acc[2 * j + 1]);
    }
    *(uint4*)(oh + (size_t)b * DN_ + lane * 8) = *(uint4*)o;
}

// ---------------- fused proj (unchanged) ----------------
#define SV_OFF 0
#define SH_OFF 33792
#define SW0_OFF 67584
#define SW1_OFF 101376
#define FPROJ_SMEM 135168

__device__ __forceinline__ void load_rows64(uint32_t sdst, const bf16* gsrc, int tid) {
#pragma unroll
    for (int i = 0; i < 8; i++) {
        int e = tid + i * 256;
        int row = e >> 5, seg = e & 31;
        cp16(sdst + (uint32_t)(row * TSF + seg * 8) * 2, gsrc + (size_t)row * DN_ + seg * 8);
    }
}

__global__ void __launch_bounds__(256, 1) fused_proj_kernel(
        const float* __restrict__ b1a, const float* __restrict__ b2a,
        const float* __restrict__ b1b, const float* __restrict__ b2b) {
    extern __shared__ char smem_dyn[];
    __shared__ float s_ss[64];
    uint32_t sb = (uint32_t)__cvta_generic_to_shared(smem_dyn);
    uint32_t sV = sb + SV_OFF, sH = sb + SH_OFF;
    uint32_t sW[2] = { sb + SW0_OFF, sb + SW1_OFF };

    int tid = threadIdx.x;
    int lane = tid & 31, w = tid >> 5;
    int wr = w >> 1, wc = w & 1;
    int grp = lane >> 2, qp = (lane & 3) * 2;
    int bm = blockIdx.x * 64;
    int view = blockIdx.z;
    const bf16* V  = view ? g_v2 : g_v1;
    const bf16* Wa = view ? g_w2at : g_w1at;
    const bf16* Wb = view ? g_w2bt : g_w1bt;
    const float* ba = view ? b2a : b1a;
    const float* bb = view ? b2b : b1b;
    bf16* Z = view ? g_z2 : g_z1;

    if (tid < 64) s_ss[tid] = 0.f;

    int rowA = (lane & 7) + ((lane >> 3) & 1) * 8;
    int kA   = (lane >> 4) * 8;
    int rowB = (lane & 7) + (lane >> 4) * 8;
    int kB   = ((lane >> 3) & 1) * 8;

    load_rows64(sV, V + (size_t)bm * DN_, tid);
    load_rows64(sW[0], Wa, tid);
    cpcommit();

    float c2[2][4][4] = {};

#pragma unroll 1
    for (int c = 0; c < 4; c++) {
        cpwait<0>();
        __syncthreads();
        if (c < 3)      load_rows64(sW[(c + 1) & 1], Wa + (size_t)(c + 1) * 64 * DN_, tid);
        else            load_rows64(sW[(c + 1) & 1], Wb, tid);
        cpcommit();

        uint32_t sWc = sW[c & 1];
        float c1[4][4] = {};
#pragma unroll
        for (int kk = 0; kk < 256; kk += 16) {
            unsigned a[4];
            ldsm4(a, sV + (uint32_t)((wr * 16 + rowA) * TSF + kk + kA) * 2);
            unsigned bfrag[4][2];
#pragma unroll
            for (int np = 0; np < 2; np++) {
                unsigned r[4];
                ldsm4(r, sWc + (uint32_t)((wc * 32 + np * 16 + rowB) * TSF + kk + kB) * 2);
                bfrag[2 * np][0] = r[0]; bfrag[2 * np][1] = r[1];
                bfrag[2 * np + 1][0] = r[2]; bfrag[2 * np + 1][1] = r[3];
            }
#pragma unroll
            for (int ns = 0; ns < 4; ns++)
                mma16816(c1[ns], a[0], a[1], a[2], a[3], bfrag[ns][0], bfrag[ns][1]);
        }
#pragma unroll
        for (int ns = 0; ns < 4; ns++) {
            int col = c * 64 + wc * 32 + ns * 8 + qp;
            float bias0 = ba[col], bias1 = ba[col + 1];
#pragma unroll
            for (int h = 0; h < 2; h++) {
                int row = wr * 16 + grp + 8 * h;
                float v0 = fmaxf(c1[ns][2 * h + 0] + bias0, 0.f);
                float v1 = fmaxf(c1[ns][2 * h + 1] + bias1, 0.f);
                __nv_bfloat162 hp;
                hp.x = __float2bfloat16(v0); hp.y = __float2bfloat16(v1);
                *(__nv_bfloat162*)(smem_dyn + SH_OFF + (size_t)(row * TSF + col) * 2) = hp;
            }
        }
    }

#pragma unroll 1
    for (int c = 0; c < 2; c++) {
        cpwait<0>();
        __syncthreads();
        if (c < 1) { load_rows64(sW[(4 + c + 1) & 1], Wb + (size_t)64 * DN_, tid); cpcommit(); }

        uint32_t sWc = sW[(4 + c) & 1];
#pragma unroll
        for (int kk = 0; kk < 256; kk += 16) {
            unsigned a[4];
            ldsm4(a, sH + (uint32_t)((wr * 16 + rowA) * TSF + kk + kA) * 2);
            unsigned bfrag[4][2];
#pragma unroll
            for (int np = 0; np < 2; np++) {
                unsigned r[4];
                ldsm4(r, sWc + (uint32_t)((wc * 32 + np * 16 + rowB) * TSF + kk + kB) * 2);
                bfrag[2 * np][0] = r[0]; bfrag[2 * np][1] = r[1];
                bfrag[2 * np + 1][0] = r[2]; bfrag[2 * np + 1][1] = r[3];
            }
#pragma unroll
            for (int ns = 0; ns < 4; ns++)
                mma16816(c2[c][ns], a[0], a[1], a[2], a[3], bfrag[ns][0], bfrag[ns][1]);
        }
    }

    float vv[2][4][4];
#pragma unroll
    for (int c = 0; c < 2; c++)
#pragma unroll
        for (int ns = 0; ns < 4; ns++) {
            int col = c * 64 + wc * 32 + ns * 8 + qp;
            float bias0 = bb[col], bias1 = bb[col + 1];
#pragma unroll
            for (int h = 0; h < 2; h++) {
                vv[c][ns][2 * h + 0] = c2[c][ns][2 * h + 0] + bias0;
                vv[c][ns][2 * h + 1] = c2[c][ns][2 * h + 1] + bias1;
            }
        }
#pragma unroll
    for (int h = 0; h < 2; h++) {
        float ss = 0.f;
#pragma unroll
        for (int c = 0; c < 2; c++)
#pragma unroll
            for (int ns = 0; ns < 4; ns++) {
                float a = vv[c][ns][2 * h + 0], b = vv[c][ns][2 * h + 1];
                ss = fmaf(a, a, ss); ss = fmaf(b, b, ss);
            }
        ss += __shfl_xor_sync(0xFFFFFFFFu, ss, 1);
        ss += __shfl_xor_sync(0xFFFFFFFFu, ss, 2);
        if ((lane & 3) == 0)
            atomicAdd(&s_ss[wr * 16 + grp + 8 * h], ss);
    }
    __syncthreads();

#pragma unroll
    for (int h = 0; h < 2; h++) {
        int rloc = wr * 16 + grp + 8 * h;
        float rinv = rsqrtf(s_ss[rloc]);
        int row = bm + rloc;
#pragma unroll
        for (int c = 0; c < 2; c++)
#pragma unroll
            for (int ns = 0; ns < 4; ns++) {
                int col = c * 64 + wc * 32 + ns * 8 + qp;
                float v0 = vv[c][ns][2 * h + 0] * rinv;
                float v1 = vv[c][ns][2 * h + 1] * rinv;
                __nv_bfloat162 hp;
                hp.x = __float2bfloat16(v0); hp.y = __float2bfloat16(v1);
                *(__nv_bfloat162*)(Z + (size_t)row * DH_ + col) = hp;
            }
    }
}

// ---------------- sim (unchanged from round 16) ----------------
__global__ void __launch_bounds__(256, 2) sim_lse_kernel() {
    extern __shared__ char smem_dyn[];
    __shared__ float s_rs[128], s_cs[2][128];
    int tid = threadIdx.x;
    int lane = tid & 31, w = tid >> 5;
    int wr = w >> 2, wc = w & 3;
    int grp = lane >> 2, qp = (lane & 3) * 2;
    int bm = blockIdx.x * 128, bn0 = blockIdx.y * 256;
    if (tid < 128) { s_rs[tid] = 0.f; s_cs[0][tid] = 0.f; s_cs[1][tid] = 0.f; }

    uint32_t sA = (uint32_t)__cvta_generic_to_shared(smem_dyn);
    uint32_t sB[2] = { sA + SIM_TILE_B, sA + 2 * SIM_TILE_B };

#pragma unroll
    for (int i = 0; i < 8; i++) {
        int idx = tid + i * 256;
        int row = idx >> 4, seg = idx & 15;
        uint32_t so = (uint32_t)(row * TSK + seg * 8) * 2;
        cp16(sA + so,    g_z1 + (size_t)(bm + row) * DH_ + seg * 8);
        cp16(sB[0] + so, g_z2 + (size_t)(bn0 + row) * DH_ + seg * 8);
    }
    cpcommit();
#pragma unroll
    for (int i = 0; i < 8; i++) {
        int idx = tid + i * 256;
        int row = idx >> 4, seg = idx & 15;
        cp16(sB[1] + (uint32_t)(row * TSK + seg * 8) * 2,
             g_z2 + (size_t)(bn0 + 128 + row) * DH_ + seg * 8);
    }
    cpcommit();

    int rowA = (lane & 7) + ((lane >> 3) & 1) * 8;
    int kA   = (lane >> 4) * 8;
    int rowB = (lane & 7) + (lane >> 4) * 8;
    int kB   = ((lane >> 3) & 1) * 8;

    float rs[4][2] = {};

#pragma unroll 1
    for (int j = 0; j < 2; j++) {
        if (j == 0) { cpwait<1>(); } else { cpwait<0>(); }
        __syncthreads();
        int bn = bn0 + j * 128;
        uint32_t sBj = sB[j];
        bool diag_tile = (bm == bn);

        float c[4][4][4] = {};
#pragma unroll
        for (int kk = 0; kk < 128; kk += 16) {
            unsigned a[4][4];
#pragma unroll
            for (int ms = 0; ms < 4; ms++)
                ldsm4(a[ms], sA + (uint32_t)(((wr * 4 + ms) * 16 + rowA) * TSK + kk + kA) * 2);
            unsigned bfr[4][2];
#pragma unroll
            for (int np = 0; np < 2; np++) {
                unsigned r[4];
                ldsm4(r, sBj + (uint32_t)((wc * 32 + np * 16 + rowB) * TSK + kk + kB) * 2);
                bfr[2 * np][0] = r[0]; bfr[2 * np][1] = r[1];
                bfr[2 * np + 1][0] = r[2]; bfr[2 * np + 1][1] = r[3];
            }
#pragma unroll
            for (int ms = 0; ms < 4; ms++)
#pragma unroll
                for (int ns = 0; ns < 4; ns++)
                    mma16816(c[ms][ns], a[ms][0], a[ms][1], a[ms][2], a[ms][3], bfr[ns][0], bfr[ns][1]);
        }

        if (diag_tile) {
#pragma unroll
            for (int ms = 0; ms < 4; ms++)
#pragma unroll
                for (int ns = 0; ns < 4; ns++)
#pragma unroll
                    for (int r = 0; r < 4; r++) {
                        int h = r >> 1, p = r & 1;
                        int rloc = (wr * 4 + ms) * 16 + grp + 8 * h;
                        int cloc = wc * 32 + ns * 8 + qp + p;
                        if (rloc == cloc) g_diag[bm + rloc] = c[ms][ns][r] * INV_T;
                    }
        }

        float cs[4][2] = {};
#pragma unroll
        for (int ms = 0; ms < 4; ms++) {
#pragma unroll
            for (int ns = 0; ns < 4; ns++) {
#pragma unroll
                for (int r = 0; r < 4; r++) {
                    int h = r >> 1, p = r & 1;
                    float ev = ex2f(fmaf(c[ms][ns][r], K2E, -K2E));
                    rs[ms][h] += ev;
                    cs[ns][p] += ev;
                }
            }
        }
#pragma unroll
        for (int ns = 0; ns < 4; ns++)
#pragma unroll
            for (int p = 0; p < 2; p++) {
                float v = cs[ns][p];
                v += __shfl_xor_sync(0xFFFFFFFFu, v, 4);
                v += __shfl_xor_sync(0xFFFFFFFFu, v, 8);
                v += __shfl_xor_sync(0xFFFFFFFFu, v, 16);
                if (grp == 0)
                    atomicAdd(&s_cs[j][wc * 32 + ns * 8 + qp + p], v);
            }
    }

#pragma unroll
    for (int ms = 0; ms < 4; ms++)
#pragma unroll
        for (int h = 0; h < 2; h++) {
            float v = rs[ms][h];
            v += __shfl_xor_sync(0xFFFFFFFFu, v, 1);
            v += __shfl_xor_sync(0xFFFFFFFFu, v, 2);
            if ((lane & 3) == 0)
                atomicAdd(&s_rs[(wr * 4 + ms) * 16 + grp + 8 * h], v);
        }
    __syncthreads();
    if (tid < 128) {
        atomicAdd(&g_rowsum[bm + tid], s_rs[tid]);
        atomicAdd(&g_colsum[bn0 + tid], s_cs[0][tid]);
        atomicAdd(&g_colsum[bn0 + 128 + tid], s_cs[1][tid]);
    }
}

// ---------------- final loss reduce ----------------
__global__ void loss_kernel(float* __restrict__ out) {
    float acc = 0.f;
    for (int i = threadIdx.x; i < BN_; i += 256) {
        acc += 0.5f * (logf(g_rowsum[i]) + logf(g_colsum[i])) + INV_T - g_diag[i];
    }
#pragma unroll
    for (int off = 16; off; off >>= 1) acc += __shfl_xor_sync(0xFFFFFFFFu, acc, off);
    __shared__ float wsum[8];
    if ((threadIdx.x & 31) == 0) wsum[threadIdx.x >> 5] = acc;
    __syncthreads();
    if (threadIdx.x == 0) {
        float tot = 0.f;
        for (int k = 0; k < 8; k++) tot += wsum[k];
        out[0] = tot / (float)BN_;
    }
}

// ---------------- launch ----------------
extern "C" void kernel_launch(void* const* d_in, const int* in_sizes, int n_in,
                              void* d_out, int out_size) {
    const float* nf   = (const float*)d_in[0];
    const float* rel  = (const float*)d_in[1];
    const int*   nb1  = (const int*)d_in[2];
    const int*   rl1  = (const int*)d_in[3];
    const void*  m1   = d_in[4];
    const int*   nb2  = (const int*)d_in[5];
    const int*   rl2  = (const int*)d_in[6];
    const void*  m2   = d_in[7];
    const int*   self_ = (const int*)d_in[8];
    const float* W1a  = (const float*)d_in[9];
    const float* b1a  = (const float*)d_in[10];
    const float* W1b  = (const float*)d_in[11];
    const float* b1b  = (const float*)d_in[12];
    const float* W2a  = (const float*)d_in[13];
    const float* b2a  = (const float*)d_in[14];
    const float* W2b  = (const float*)d_in[15];
    const float* b2b  = (const float*)d_in[16];

    const int smemS = 3 * SIM_TILE_B;   // 104448
    cudaFuncSetAttribute(fused_proj_kernel, cudaFuncAttributeMaxDynamicSharedMemorySize, FPROJ_SMEM);
    cudaFuncSetAttribute(sim_lse_kernel,    cudaFuncAttributeMaxDynamicSharedMemorySize, smemS);

    detect_kernel<<<1, 256>>>((const unsigned int*)m1);
    agg_prep_kernel<<<1072, 256>>>(nf, rel, nb1, rl1, m1, nb2, rl2, m2, self_,
                                   W1a, W1b, W2a, W2b);
    fused_proj_kernel<<<dim3(64, 1, 2), 256, FPROJ_SMEM>>>(b1a, b2a, b1b, b2b);
    sim_lse_kernel<<<dim3(32, 16), 256, smemS>>>();
    loss_kernel<<<1, 256>>>((float*)d_out);
}